// round 2
// baseline (speedup 1.0000x reference)
#include <cuda_runtime.h>
#include <mma.h>
#include <cstdint>

using namespace nvcuda;

#define B_   32
#define S_   128
#define T_   128
#define E_   128
#define H_   256
#define G4_  1024
#define V_   32000
#define NCTA_REC 128

// ---------------- scratch (device globals; no allocation) ----------------
__device__ float   g_xg[(size_t)(2 * B_ * S_) * G4_];   // [8192][1024] enc then dec
__device__ float   g_dec_out[(size_t)B_ * T_ * H_];     // [B*T][H]
__device__ float4  g_h4[2 * (B_ * H_ / 4)];             // ping-pong h state
__device__ unsigned g_bar_count;
__device__ unsigned g_bar_epoch;

// =================== K1: embedding gather + input-gate GEMM ===============
// xg[m][g] = sum_e emb[tok(m)][e] * Wih[g][e] + (bih[g]+bhh[g]),  m in [0,8192)
// grid: 256 row-tiles (32 rows) x 4 col-tiles (256 cols) = 1024 CTAs, 256 thr
__global__ void __launch_bounds__(256, 1) xg_kernel(
    const int* __restrict__ x, const int* __restrict__ y,
    const float* __restrict__ enc_emb, const float* __restrict__ dec_emb,
    const float* __restrict__ Wih_enc, const float* __restrict__ bih_enc,
    const float* __restrict__ bhh_enc,
    const float* __restrict__ Wih_dec, const float* __restrict__ bih_dec,
    const float* __restrict__ bhh_dec)
{
    extern __shared__ float sm[];
    float4* w_s4 = (float4*)sm;                    // [256][33] float4 (stride 132 floats)
    float4* e_s4 = (float4*)(sm + 256 * 132);      // [32][33]
    __shared__ int tok_s[32];

    const int tid = threadIdx.x;
    const int rt = blockIdx.x >> 2;
    const int ct = blockIdx.x & 3;
    const int rowbase = rt * 32;
    const bool enc = rowbase < (B_ * S_);

    const float* Wih = enc ? Wih_enc : Wih_dec;
    const float* emb = enc ? enc_emb : dec_emb;
    const float* bih = enc ? bih_enc : bih_dec;
    const float* bhh = enc ? bhh_enc : bhh_dec;
    const int*  toks = enc ? x : y;
    const int   rb   = enc ? rowbase : rowbase - B_ * S_;  // local = b*128 + t

    // stage weight tile: 256 gate rows x 128 cols
    const int g0 = ct * 256;
    const float4* W4 = (const float4*)(Wih + (size_t)g0 * E_);
    #pragma unroll
    for (int i = 0; i < 32; ++i) {
        int fi = tid + i * 256;            // 0..8191
        int gr = fi >> 5, e4 = fi & 31;
        w_s4[gr * 33 + e4] = W4[gr * 32 + e4];
    }
    if (tid < 32) tok_s[tid] = toks[rb + tid];
    __syncthreads();

    // stage 32 embedding rows
    #pragma unroll
    for (int i = 0; i < 4; ++i) {
        int fi = tid + i * 256;            // 0..1023
        int r = fi >> 5, e4 = fi & 31;
        e_s4[r * 33 + e4] = ((const float4*)emb)[(size_t)tok_s[r] * 32 + e4];
    }
    __syncthreads();

    float acc[32];
    #pragma unroll
    for (int r = 0; r < 32; ++r) acc[r] = 0.f;

    const int c = tid;
    #pragma unroll 8
    for (int e4 = 0; e4 < 32; ++e4) {
        float4 wv = w_s4[c * 33 + e4];
        #pragma unroll
        for (int r = 0; r < 32; ++r) {
            float4 ev = e_s4[r * 33 + e4];       // broadcast
            acc[r] = fmaf(wv.x, ev.x, acc[r]);
            acc[r] = fmaf(wv.y, ev.y, acc[r]);
            acc[r] = fmaf(wv.z, ev.z, acc[r]);
            acc[r] = fmaf(wv.w, ev.w, acc[r]);
        }
    }
    const int g = g0 + c;
    const float bias = bih[g] + bhh[g];
    #pragma unroll
    for (int r = 0; r < 32; ++r)
        g_xg[(size_t)(rowbase + r) * G4_ + g] = acc[r] + bias;
}

// =================== K2: persistent LSTM recurrence ========================
__device__ __forceinline__ void grid_barrier() {
    __syncthreads();
    if (threadIdx.x == 0) {
        unsigned e = *((volatile unsigned*)&g_bar_epoch);
        __threadfence();
        unsigned prev = atomicAdd(&g_bar_count, 1u);
        if (prev == NCTA_REC - 1) {
            atomicExch(&g_bar_count, 0u);
            __threadfence();
            atomicAdd(&g_bar_epoch, 1u);
        } else {
            while (*((volatile unsigned*)&g_bar_epoch) == e) { __nanosleep(64); }
        }
        __threadfence();
    }
    __syncthreads();
}

__device__ __forceinline__ float sigf(float v) { return 1.f / (1.f + expf(-v)); }

// 128 CTAs x 256 threads. CTA owns hidden units u0, u0+1 (8 gate rows).
// Whh rows resident in SMEM for the whole launch; h ping-pong in global.
__global__ void __launch_bounds__(256, 1) rec_kernel(
    const float* __restrict__ Whh_enc, const float* __restrict__ Whh_dec)
{
    __shared__ float4 w_s4[8 * 64];     // 8 rows x 256 fp32
    __shared__ float4 h_s4[32 * 65];    // 32 x 260 (padded, conflict-free f4)
    __shared__ float  gates_s[8 * 32];
    __shared__ float  c_s[64];

    const int tid = threadIdx.x;
    const int u0  = blockIdx.x * 2;

    const int r = tid >> 5;             // row slot 0..7  (gate = r>>1, unit = r&1)
    const int b = tid & 31;
    const int grow = (r >> 1) * H_ + u0 + (r & 1);

    // load encoder Whh rows
    {
        const float4* W4 = (const float4*)Whh_enc;
        #pragma unroll
        for (int i = 0; i < 2; ++i) {
            int fi = tid + i * 256;                 // 0..511
            int rr = fi >> 6, k4 = fi & 63;
            int gg = (rr >> 1) * H_ + u0 + (rr & 1);
            w_s4[rr * 64 + k4] = W4[(size_t)gg * 64 + k4];
        }
    }
    // init h (buffer 0) and c
    if (tid < 64) {
        int ul2 = tid >> 5, b2 = tid & 31;
        ((float*)g_h4)[b2 * H_ + u0 + ul2] = 0.f;
        c_s[tid] = 0.f;
        __threadfence();
    }
    grid_barrier();

    for (int step = 0; step < S_ + T_; ++step) {
        const bool dec = (step >= S_);
        const int  t   = dec ? step - S_ : step;
        const int  rdo = (step & 1) * 2048;                 // read buffer (float4)
        const int  wro = ((step + 1) & 1) * (B_ * H_);      // write buffer (float)

        // pull full h into SMEM (L2 path — other SMs wrote it last step)
        #pragma unroll
        for (int i = 0; i < 8; ++i) {
            int fi = tid + i * 256;                // 0..2047
            int bb = fi >> 6, k4 = fi & 63;
            h_s4[bb * 65 + k4] = __ldcg(&g_h4[rdo + fi]);
        }
        __syncthreads();

        // dot(Whh[grow,:], h[b,:])
        float4 a = make_float4(0.f, 0.f, 0.f, 0.f);
        #pragma unroll
        for (int k4 = 0; k4 < 64; ++k4) {
            float4 wv = w_s4[r * 64 + k4];         // broadcast
            float4 hv = h_s4[b * 65 + k4];         // conflict-free
            a.x = fmaf(wv.x, hv.x, a.x);
            a.y = fmaf(wv.y, hv.y, a.y);
            a.z = fmaf(wv.z, hv.z, a.z);
            a.w = fmaf(wv.w, hv.w, a.w);
        }
        const float* xg = g_xg + (dec ? (size_t)(B_ * S_) * G4_ : 0);
        float pre = xg[(size_t)(b * S_ + t) * G4_ + grow] + a.x + a.y + a.z + a.w;
        gates_s[r * 32 + b] = pre;
        __syncthreads();

        // elementwise LSTM cell for this CTA's 2 units x 32 batches
        if (tid < 64) {
            int ul2 = tid >> 5, b2 = tid & 31;
            float iv = sigf (gates_s[(0 + ul2) * 32 + b2]);
            float fv = sigf (gates_s[(2 + ul2) * 32 + b2]);
            float gv = tanhf(gates_s[(4 + ul2) * 32 + b2]);
            float ov = sigf (gates_s[(6 + ul2) * 32 + b2]);
            float cc = fv * c_s[tid] + iv * gv;
            c_s[tid] = cc;
            float hh = ov * tanhf(cc);
            ((float*)g_h4)[wro + b2 * H_ + u0 + ul2] = hh;
            if (dec) g_dec_out[(size_t)(b2 * T_ + t) * H_ + u0 + ul2] = hh;
            __threadfence();
        }
        grid_barrier();

        if (step == S_ - 1) {   // switch to decoder weights
            const float4* W4 = (const float4*)Whh_dec;
            #pragma unroll
            for (int i = 0; i < 2; ++i) {
                int fi = tid + i * 256;
                int rr = fi >> 6, k4 = fi & 63;
                int gg = (rr >> 1) * H_ + u0 + (rr & 1);
                w_s4[rr * 64 + k4] = W4[(size_t)gg * 64 + k4];
            }
            __syncthreads();
        }
    }
}

// =================== K3: output projection (wmma tf32) =====================
// logits[m][v] = dec_out[m,:] . W_out[v,:] + b_out[v]
// CTA tile 128(M) x 128(N); 8 warps = 4(M) x 2(N); warp tile 32x64.
#define LDC 132
__global__ void __launch_bounds__(256, 1) proj_kernel(
    const float* __restrict__ Wout, const float* __restrict__ bout,
    float* __restrict__ out)
{
    extern __shared__ float cs[];
    const int tid = threadIdx.x;
    const int w  = tid >> 5;
    const int wm = w & 3, wn = w >> 2;
    const int m0 = blockIdx.y * 128;
    const int n0 = blockIdx.x * 128;

    wmma::fragment<wmma::matrix_a, 16, 16, 8, wmma::precision::tf32, wmma::row_major> af[2];
    wmma::fragment<wmma::matrix_b, 16, 16, 8, wmma::precision::tf32, wmma::col_major> bf[4];
    wmma::fragment<wmma::accumulator, 16, 16, 8, float> cf[2][4];
    #pragma unroll
    for (int i = 0; i < 2; ++i)
        #pragma unroll
        for (int j = 0; j < 4; ++j)
            wmma::fill_fragment(cf[i][j], 0.f);

    const float* Abase = g_dec_out + (size_t)(m0 + wm * 32) * H_;
    const float* Bbase = Wout      + (size_t)(n0 + wn * 64) * H_;

    for (int k0 = 0; k0 < H_; k0 += 8) {
        #pragma unroll
        for (int i = 0; i < 2; ++i) {
            wmma::load_matrix_sync(af[i], Abase + (size_t)i * 16 * H_ + k0, H_);
            #pragma unroll
            for (int t2 = 0; t2 < af[i].num_elements; ++t2)
                af[i].x[t2] = wmma::__float_to_tf32(af[i].x[t2]);
        }
        #pragma unroll
        for (int j = 0; j < 4; ++j) {
            wmma::load_matrix_sync(bf[j], Bbase + (size_t)j * 16 * H_ + k0, H_);
            #pragma unroll
            for (int t2 = 0; t2 < bf[j].num_elements; ++t2)
                bf[j].x[t2] = wmma::__float_to_tf32(bf[j].x[t2]);
        }
        #pragma unroll
        for (int i = 0; i < 2; ++i)
            #pragma unroll
            for (int j = 0; j < 4; ++j)
                wmma::mma_sync(cf[i][j], af[i], bf[j], cf[i][j]);
    }

    #pragma unroll
    for (int i = 0; i < 2; ++i)
        #pragma unroll
        for (int j = 0; j < 4; ++j)
            wmma::store_matrix_sync(cs + (wm * 32 + i * 16) * LDC + wn * 64 + j * 16,
                                    cf[i][j], LDC, wmma::mem_row_major);
    __syncthreads();

    const float4* cs4 = (const float4*)cs;
    #pragma unroll
    for (int i = 0; i < 16; ++i) {
        int fi = tid + i * 256;            // 0..4095
        int rr = fi >> 5, c4 = fi & 31;
        float4 v  = cs4[rr * 33 + c4];
        float4 bb = *(const float4*)(bout + n0 + c4 * 4);
        v.x += bb.x; v.y += bb.y; v.z += bb.z; v.w += bb.w;
        *(float4*)(out + (size_t)(m0 + rr) * V_ + n0 + c4 * 4) = v;
    }
}

// ============================= launch ======================================
extern "C" void kernel_launch(void* const* d_in, const int* in_sizes, int n_in,
                              void* d_out, int out_size) {
    const int*   x        = (const int*)d_in[0];
    const int*   y        = (const int*)d_in[1];
    const float* enc_emb  = (const float*)d_in[2];
    const float* dec_emb  = (const float*)d_in[3];
    const float* Wih_enc  = (const float*)d_in[4];
    const float* Whh_enc  = (const float*)d_in[5];
    const float* bih_enc  = (const float*)d_in[6];
    const float* bhh_enc  = (const float*)d_in[7];
    const float* Wih_dec  = (const float*)d_in[8];
    const float* Whh_dec  = (const float*)d_in[9];
    const float* bih_dec  = (const float*)d_in[10];
    const float* bhh_dec  = (const float*)d_in[11];
    const float* Wout     = (const float*)d_in[12];
    const float* bout     = (const float*)d_in[13];
    float*       out      = (float*)d_out;

    const int XG_SMEM   = (256 * 132 + 32 * 132) * 4;   // 152064
    const int PROJ_SMEM = 128 * LDC * 4;                 // 67584

    cudaFuncSetAttribute(xg_kernel,  cudaFuncAttributeMaxDynamicSharedMemorySize, XG_SMEM);
    cudaFuncSetAttribute(proj_kernel, cudaFuncAttributeMaxDynamicSharedMemorySize, PROJ_SMEM);

    xg_kernel<<<1024, 256, XG_SMEM>>>(x, y, enc_emb, dec_emb,
                                      Wih_enc, bih_enc, bhh_enc,
                                      Wih_dec, bih_dec, bhh_dec);
    rec_kernel<<<NCTA_REC, 256>>>(Whh_enc, Whh_dec);
    proj_kernel<<<dim3(V_ / 128, (B_ * T_) / 128), 256, PROJ_SMEM>>>(Wout, bout, out);
}

// round 4
// speedup vs baseline: 1.7237x; 1.7237x over previous
#include <cuda_runtime.h>
#include <cuda_fp16.h>
#include <cstdint>

#define B_   32
#define S_   128
#define T_   128
#define E_   128
#define H_   256
#define G4_  1024
#define V_   32000
#define NCTA_REC 128

// ---------------- scratch (device globals; no allocation) ----------------
__device__ float   g_xg[(size_t)(2 * B_ * S_) * G4_];   // [8192][1024] enc then dec
__device__ float   g_dec_out[(size_t)B_ * T_ * H_];     // [B*T][H]
__device__ float4  g_h4[2 * (B_ * H_ / 4)];             // ping-pong h state
__device__ unsigned g_bar_count;
__device__ unsigned g_bar_epoch;
// fp16 operands for tensor-core projection
__device__ __half  g_ah[(size_t)B_ * T_ * H_];          // dec_out fp16 [4096][256]
__device__ __half  g_bh[(size_t)V_ * H_];               // W_out  fp16 [32000][256]

#define SWZ128(off) ((off) ^ (((off) >> 3) & 0x70))

__device__ __forceinline__ uint32_t smem_to_u32(const void* p) {
    uint32_t a;
    asm("{ .reg .u64 t; cvta.to.shared.u64 t, %1; cvt.u32.u64 %0, t; }" : "=r"(a) : "l"(p));
    return a;
}

// =================== K0: fp32 -> fp16 convert ==============================
__global__ void __launch_bounds__(256) tohalf_kernel(const float* __restrict__ src,
                                                     __half* __restrict__ dst, int n4) {
    int i = blockIdx.x * 256 + threadIdx.x;
    if (i >= n4) return;
    float4 v = ((const float4*)src)[i];
    ((__half2*)dst)[2 * i]     = __floats2half2_rn(v.x, v.y);
    ((__half2*)dst)[2 * i + 1] = __floats2half2_rn(v.z, v.w);
}

// =================== K1: embedding gather + input-gate GEMM ===============
__global__ void __launch_bounds__(256, 1) xg_kernel(
    const int* __restrict__ x, const int* __restrict__ y,
    const float* __restrict__ enc_emb, const float* __restrict__ dec_emb,
    const float* __restrict__ Wih_enc, const float* __restrict__ bih_enc,
    const float* __restrict__ bhh_enc,
    const float* __restrict__ Wih_dec, const float* __restrict__ bih_dec,
    const float* __restrict__ bhh_dec)
{
    extern __shared__ float sm[];
    float4* w_s4 = (float4*)sm;                    // [256][33] float4
    float4* e_s4 = (float4*)(sm + 256 * 132);      // [32][33]
    __shared__ int tok_s[32];

    const int tid = threadIdx.x;
    const int rt = blockIdx.x >> 2;
    const int ct = blockIdx.x & 3;
    const int rowbase = rt * 32;
    const bool enc = rowbase < (B_ * S_);

    const float* Wih = enc ? Wih_enc : Wih_dec;
    const float* emb = enc ? enc_emb : dec_emb;
    const float* bih = enc ? bih_enc : bih_dec;
    const float* bhh = enc ? bhh_enc : bhh_dec;
    const int*  toks = enc ? x : y;
    const int   rb   = enc ? rowbase : rowbase - B_ * S_;

    const int g0 = ct * 256;
    const float4* W4 = (const float4*)(Wih + (size_t)g0 * E_);
    #pragma unroll
    for (int i = 0; i < 32; ++i) {
        int fi = tid + i * 256;
        int gr = fi >> 5, e4 = fi & 31;
        w_s4[gr * 33 + e4] = W4[gr * 32 + e4];
    }
    if (tid < 32) tok_s[tid] = toks[rb + tid];
    __syncthreads();

    #pragma unroll
    for (int i = 0; i < 4; ++i) {
        int fi = tid + i * 256;
        int r = fi >> 5, e4 = fi & 31;
        e_s4[r * 33 + e4] = ((const float4*)emb)[(size_t)tok_s[r] * 32 + e4];
    }
    __syncthreads();

    float acc[32];
    #pragma unroll
    for (int r = 0; r < 32; ++r) acc[r] = 0.f;

    const int c = tid;
    #pragma unroll 8
    for (int e4 = 0; e4 < 32; ++e4) {
        float4 wv = w_s4[c * 33 + e4];
        #pragma unroll
        for (int r = 0; r < 32; ++r) {
            float4 ev = e_s4[r * 33 + e4];
            acc[r] = fmaf(wv.x, ev.x, acc[r]);
            acc[r] = fmaf(wv.y, ev.y, acc[r]);
            acc[r] = fmaf(wv.z, ev.z, acc[r]);
            acc[r] = fmaf(wv.w, ev.w, acc[r]);
        }
    }
    const int g = g0 + c;
    const float bias = bih[g] + bhh[g];
    #pragma unroll
    for (int r = 0; r < 32; ++r)
        g_xg[(size_t)(rowbase + r) * G4_ + g] = acc[r] + bias;
}

// =================== K2: persistent LSTM recurrence ========================
__device__ __forceinline__ void grid_barrier() {
    __syncthreads();
    if (threadIdx.x == 0) {
        unsigned e = *((volatile unsigned*)&g_bar_epoch);
        __threadfence();
        unsigned prev = atomicAdd(&g_bar_count, 1u);
        if (prev == NCTA_REC - 1) {
            atomicExch(&g_bar_count, 0u);
            __threadfence();
            atomicAdd(&g_bar_epoch, 1u);
        } else {
            while (*((volatile unsigned*)&g_bar_epoch) == e) { __nanosleep(64); }
        }
        __threadfence();
    }
    __syncthreads();
}

__device__ __forceinline__ float sigf(float v) { return 1.f / (1.f + expf(-v)); }

__global__ void __launch_bounds__(256, 1) rec_kernel(
    const float* __restrict__ Whh_enc, const float* __restrict__ Whh_dec)
{
    __shared__ float4 w_s4[8 * 64];
    __shared__ float4 h_s4[32 * 65];
    __shared__ float  gates_s[8 * 32];
    __shared__ float  c_s[64];

    const int tid = threadIdx.x;
    const int u0  = blockIdx.x * 2;

    const int r = tid >> 5;
    const int b = tid & 31;
    const int grow = (r >> 1) * H_ + u0 + (r & 1);

    {
        const float4* W4 = (const float4*)Whh_enc;
        #pragma unroll
        for (int i = 0; i < 2; ++i) {
            int fi = tid + i * 256;
            int rr = fi >> 6, k4 = fi & 63;
            int gg = (rr >> 1) * H_ + u0 + (rr & 1);
            w_s4[rr * 64 + k4] = W4[(size_t)gg * 64 + k4];
        }
    }
    if (tid < 64) {
        int ul2 = tid >> 5, b2 = tid & 31;
        ((float*)g_h4)[b2 * H_ + u0 + ul2] = 0.f;
        c_s[tid] = 0.f;
        __threadfence();
    }
    grid_barrier();

    for (int step = 0; step < S_ + T_; ++step) {
        const bool dec = (step >= S_);
        const int  t   = dec ? step - S_ : step;
        const int  rdo = (step & 1) * 2048;
        const int  wro = ((step + 1) & 1) * (B_ * H_);

        #pragma unroll
        for (int i = 0; i < 8; ++i) {
            int fi = tid + i * 256;
            int bb = fi >> 6, k4 = fi & 63;
            h_s4[bb * 65 + k4] = __ldcg(&g_h4[rdo + fi]);
        }
        __syncthreads();

        float4 a = make_float4(0.f, 0.f, 0.f, 0.f);
        #pragma unroll
        for (int k4 = 0; k4 < 64; ++k4) {
            float4 wv = w_s4[r * 64 + k4];
            float4 hv = h_s4[b * 65 + k4];
            a.x = fmaf(wv.x, hv.x, a.x);
            a.y = fmaf(wv.y, hv.y, a.y);
            a.z = fmaf(wv.z, hv.z, a.z);
            a.w = fmaf(wv.w, hv.w, a.w);
        }
        const float* xg = g_xg + (dec ? (size_t)(B_ * S_) * G4_ : 0);
        float pre = xg[(size_t)(b * S_ + t) * G4_ + grow] + a.x + a.y + a.z + a.w;
        gates_s[r * 32 + b] = pre;
        __syncthreads();

        if (tid < 64) {
            int ul2 = tid >> 5, b2 = tid & 31;
            float iv = sigf (gates_s[(0 + ul2) * 32 + b2]);
            float fv = sigf (gates_s[(2 + ul2) * 32 + b2]);
            float gv = tanhf(gates_s[(4 + ul2) * 32 + b2]);
            float ov = sigf (gates_s[(6 + ul2) * 32 + b2]);
            float cc = fv * c_s[tid] + iv * gv;
            c_s[tid] = cc;
            float hh = ov * tanhf(cc);
            ((float*)g_h4)[wro + b2 * H_ + u0 + ul2] = hh;
            if (dec) g_dec_out[(size_t)(b2 * T_ + t) * H_ + u0 + ul2] = hh;
            __threadfence();
        }
        grid_barrier();

        if (step == S_ - 1) {
            const float4* W4 = (const float4*)Whh_dec;
            #pragma unroll
            for (int i = 0; i < 2; ++i) {
                int fi = tid + i * 256;
                int rr = fi >> 6, k4 = fi & 63;
                int gg = (rr >> 1) * H_ + u0 + (rr & 1);
                w_s4[rr * 64 + k4] = W4[(size_t)gg * 64 + k4];
            }
            __syncthreads();
        }
    }
}

// =================== K3: output projection (fp16 mma.sync) =================
// out[4096, 32000] = Ah[4096,256] . Bh[32000,256]^T + bias
// CTA tile 128x128, K-chunks of 64, 2-stage cp.async pipeline.
// 8 warps = 2(M) x 4(N); warp tile 64x32; mma m16n8k16 row.col fp16->fp32.
#define PROJ_SMEM (2 * 32768)

__device__ __forceinline__ void ldm_x4(uint32_t& r0, uint32_t& r1, uint32_t& r2, uint32_t& r3,
                                       uint32_t addr) {
    asm volatile("ldmatrix.sync.aligned.m8n8.x4.shared.b16 {%0,%1,%2,%3}, [%4];"
                 : "=r"(r0), "=r"(r1), "=r"(r2), "=r"(r3) : "r"(addr));
}
__device__ __forceinline__ void ldm_x2(uint32_t& r0, uint32_t& r1, uint32_t addr) {
    asm volatile("ldmatrix.sync.aligned.m8n8.x2.shared.b16 {%0,%1}, [%2];"
                 : "=r"(r0), "=r"(r1) : "r"(addr));
}
__device__ __forceinline__ void mma16816(float* d, const uint32_t* a, const uint32_t* b) {
    asm volatile(
        "mma.sync.aligned.m16n8k16.row.col.f32.f16.f16.f32 "
        "{%0,%1,%2,%3}, {%4,%5,%6,%7}, {%8,%9}, {%0,%1,%2,%3};"
        : "+f"(d[0]), "+f"(d[1]), "+f"(d[2]), "+f"(d[3])
        : "r"(a[0]), "r"(a[1]), "r"(a[2]), "r"(a[3]), "r"(b[0]), "r"(b[1]));
}

__global__ void __launch_bounds__(256, 2) proj_kernel(const float* __restrict__ bout,
                                                      float* __restrict__ out)
{
    extern __shared__ char smem[];
    const uint32_t sbase = smem_to_u32(smem);
    const int tid  = threadIdx.x;
    const int lane = tid & 31;
    const int w    = tid >> 5;
    const int wm   = w >> 2;          // 0..1
    const int wn   = w & 3;           // 0..3
    const int m0   = blockIdx.x * 128;
    const int n0   = blockIdx.y * 128;

    // stage s: A tile [128][64]h at s*32768, B tile [128][64]h at s*32768+16384
    auto issue_chunk = [&](int c, int s) {
        const uint32_t abuf = sbase + s * 32768;
        const uint32_t bbuf = abuf + 16384;
        const __half* Ag = g_ah + (size_t)m0 * H_ + c * 64;
        const __half* Bg = g_bh + (size_t)n0 * H_ + c * 64;
        #pragma unroll
        for (int j = 0; j < 4; ++j) {
            int fi = tid + j * 256;            // 0..1023
            int row = fi >> 3, c8 = fi & 7;
            uint32_t soff = SWZ128((uint32_t)(row * 128 + c8 * 16));
            const void* ga = (const char*)(Ag + (size_t)row * H_ + c8 * 8);
            const void* gb = (const char*)(Bg + (size_t)row * H_ + c8 * 8);
            asm volatile("cp.async.cg.shared.global [%0], [%1], 16;" :: "r"(abuf + soff), "l"(ga));
            asm volatile("cp.async.cg.shared.global [%0], [%1], 16;" :: "r"(bbuf + soff), "l"(gb));
        }
        asm volatile("cp.async.commit_group;" ::: "memory");
    };

    float acc[4][4][4];
    #pragma unroll
    for (int i = 0; i < 4; ++i)
        #pragma unroll
        for (int j = 0; j < 4; ++j)
            #pragma unroll
            for (int k = 0; k < 4; ++k) acc[i][j][k] = 0.f;

    issue_chunk(0, 0);
    issue_chunk(1, 1);

    const int l16 = lane & 15;
    #pragma unroll 1
    for (int c = 0; c < 4; ++c) {
        if (c < 3) asm volatile("cp.async.wait_group 1;" ::: "memory");
        else       asm volatile("cp.async.wait_group 0;" ::: "memory");
        __syncthreads();

        const uint32_t abuf = sbase + (c & 1) * 32768;
        const uint32_t bbuf = abuf + 16384;

        #pragma unroll
        for (int ks = 0; ks < 4; ++ks) {
            uint32_t a[4][4], b[4][2];
            #pragma unroll
            for (int mi = 0; mi < 4; ++mi) {
                int row = wm * 64 + mi * 16 + l16;
                uint32_t off = (uint32_t)(row * 128 + ks * 32 + (lane >> 4) * 16);
                ldm_x4(a[mi][0], a[mi][1], a[mi][2], a[mi][3], abuf + SWZ128(off));
            }
            #pragma unroll
            for (int bi = 0; bi < 4; ++bi) {
                int row = wn * 32 + bi * 8 + (l16 & 7);
                uint32_t off = (uint32_t)(row * 128 + ks * 32 + (l16 >> 3) * 16);
                ldm_x2(b[bi][0], b[bi][1], bbuf + SWZ128(off));
            }
            #pragma unroll
            for (int mi = 0; mi < 4; ++mi)
                #pragma unroll
                for (int bi = 0; bi < 4; ++bi)
                    mma16816(acc[mi][bi], a[mi], b[bi]);
        }
        __syncthreads();
        if (c + 2 < 4) issue_chunk(c + 2, c & 1);
    }

    // epilogue: direct float2 stores + bias
    #pragma unroll
    for (int bi = 0; bi < 4; ++bi) {
        const int col = n0 + wn * 32 + bi * 8 + (lane & 3) * 2;
        const float2 bb = *(const float2*)(bout + col);
        #pragma unroll
        for (int mi = 0; mi < 4; ++mi) {
            const int row = m0 + wm * 64 + mi * 16 + (lane >> 2);
            float2 v0 = make_float2(acc[mi][bi][0] + bb.x, acc[mi][bi][1] + bb.y);
            float2 v1 = make_float2(acc[mi][bi][2] + bb.x, acc[mi][bi][3] + bb.y);
            *(float2*)(out + (size_t)row * V_ + col) = v0;
            *(float2*)(out + (size_t)(row + 8) * V_ + col) = v1;
        }
    }
}

// ============================= launch ======================================
extern "C" void kernel_launch(void* const* d_in, const int* in_sizes, int n_in,
                              void* d_out, int out_size) {
    const int*   x        = (const int*)d_in[0];
    const int*   y        = (const int*)d_in[1];
    const float* enc_emb  = (const float*)d_in[2];
    const float* dec_emb  = (const float*)d_in[3];
    const float* Wih_enc  = (const float*)d_in[4];
    const float* Whh_enc  = (const float*)d_in[5];
    const float* bih_enc  = (const float*)d_in[6];
    const float* bhh_enc  = (const float*)d_in[7];
    const float* Wih_dec  = (const float*)d_in[8];
    const float* Whh_dec  = (const float*)d_in[9];
    const float* bih_dec  = (const float*)d_in[10];
    const float* bhh_dec  = (const float*)d_in[11];
    const float* Wout     = (const float*)d_in[12];
    const float* bout     = (const float*)d_in[13];
    float*       out      = (float*)d_out;

    const int XG_SMEM = (256 * 132 + 32 * 132) * 4;

    cudaFuncSetAttribute(xg_kernel, cudaFuncAttributeMaxDynamicSharedMemorySize, XG_SMEM);
    cudaFuncSetAttribute(proj_kernel, cudaFuncAttributeMaxDynamicSharedMemorySize, PROJ_SMEM);

    __half *ah, *bh;
    float *dec_out_p;
    cudaGetSymbolAddress((void**)&ah, g_ah);
    cudaGetSymbolAddress((void**)&bh, g_bh);
    cudaGetSymbolAddress((void**)&dec_out_p, g_dec_out);

    // convert W_out to fp16 (independent of recurrence)
    tohalf_kernel<<<(V_ * H_ / 4 + 255) / 256, 256>>>(Wout, bh, V_ * H_ / 4);

    xg_kernel<<<1024, 256, XG_SMEM>>>(x, y, enc_emb, dec_emb,
                                      Wih_enc, bih_enc, bhh_enc,
                                      Wih_dec, bih_dec, bhh_dec);
    rec_kernel<<<NCTA_REC, 256>>>(Whh_enc, Whh_dec);

    // convert dec_out to fp16 after recurrence
    tohalf_kernel<<<(B_ * T_ * H_ / 4 + 255) / 256, 256>>>(dec_out_p, ah, B_ * T_ * H_ / 4);

    proj_kernel<<<dim3(32, V_ / 128), 256, PROJ_SMEM>>>(bout, out);
}

// round 5
// speedup vs baseline: 2.5077x; 1.4548x over previous
#include <cuda_runtime.h>
#include <cuda_fp16.h>
#include <cstdint>

#define B_   32
#define S_   128
#define T_   128
#define E_   128
#define H_   256
#define G4_  1024
#define V_   32000
#define NCTA_REC 128

// ---------------- scratch (device globals; no allocation) ----------------
__device__ float   g_xg[(size_t)(2 * B_ * S_) * G4_];   // [8192][1024] enc then dec
__device__ float   g_h[2 * B_ * H_];                    // ping-pong h, layout [b][u]
__device__ unsigned g_bar_count;
// fp16 operands for tensor-core projection
__device__ __half  g_ah[(size_t)B_ * T_ * H_];          // dec_out fp16 [4096][256]
__device__ __half  g_bh[(size_t)V_ * H_];               // W_out  fp16 [32000][256]

#define SWZ128(off) ((off) ^ (((off) >> 3) & 0x70))

__device__ __forceinline__ uint32_t smem_to_u32(const void* p) {
    uint32_t a;
    asm("{ .reg .u64 t; cvta.to.shared.u64 t, %1; cvt.u32.u64 %0, t; }" : "=r"(a) : "l"(p));
    return a;
}

// =================== K_zero: reset barrier counter per replay ==============
__global__ void zero_kernel() { g_bar_count = 0u; }

// =================== K0: fp32 -> fp16 convert ==============================
__global__ void __launch_bounds__(256) tohalf_kernel(const float* __restrict__ src,
                                                     __half* __restrict__ dst, int n4) {
    int i = blockIdx.x * 256 + threadIdx.x;
    if (i >= n4) return;
    float4 v = ((const float4*)src)[i];
    ((__half2*)dst)[2 * i]     = __floats2half2_rn(v.x, v.y);
    ((__half2*)dst)[2 * i + 1] = __floats2half2_rn(v.z, v.w);
}

// =================== K1: embedding gather + input-gate GEMM ===============
__global__ void __launch_bounds__(256, 1) xg_kernel(
    const int* __restrict__ x, const int* __restrict__ y,
    const float* __restrict__ enc_emb, const float* __restrict__ dec_emb,
    const float* __restrict__ Wih_enc, const float* __restrict__ bih_enc,
    const float* __restrict__ bhh_enc,
    const float* __restrict__ Wih_dec, const float* __restrict__ bih_dec,
    const float* __restrict__ bhh_dec)
{
    extern __shared__ float sm[];
    float4* w_s4 = (float4*)sm;                    // [256][33] float4
    float4* e_s4 = (float4*)(sm + 256 * 132);      // [32][33]
    __shared__ int tok_s[32];

    const int tid = threadIdx.x;
    const int rt = blockIdx.x >> 2;
    const int ct = blockIdx.x & 3;
    const int rowbase = rt * 32;
    const bool enc = rowbase < (B_ * S_);

    const float* Wih = enc ? Wih_enc : Wih_dec;
    const float* emb = enc ? enc_emb : dec_emb;
    const float* bih = enc ? bih_enc : bih_dec;
    const float* bhh = enc ? bhh_enc : bhh_dec;
    const int*  toks = enc ? x : y;
    const int   rb   = enc ? rowbase : rowbase - B_ * S_;

    const int g0 = ct * 256;
    const float4* W4 = (const float4*)(Wih + (size_t)g0 * E_);
    #pragma unroll
    for (int i = 0; i < 32; ++i) {
        int fi = tid + i * 256;
        int gr = fi >> 5, e4 = fi & 31;
        w_s4[gr * 33 + e4] = W4[gr * 32 + e4];
    }
    if (tid < 32) tok_s[tid] = toks[rb + tid];
    __syncthreads();

    #pragma unroll
    for (int i = 0; i < 4; ++i) {
        int fi = tid + i * 256;
        int r = fi >> 5, e4 = fi & 31;
        e_s4[r * 33 + e4] = ((const float4*)emb)[(size_t)tok_s[r] * 32 + e4];
    }
    __syncthreads();

    float acc[32];
    #pragma unroll
    for (int r = 0; r < 32; ++r) acc[r] = 0.f;

    const int c = tid;
    #pragma unroll 8
    for (int e4 = 0; e4 < 32; ++e4) {
        float4 wv = w_s4[c * 33 + e4];
        #pragma unroll
        for (int r = 0; r < 32; ++r) {
            float4 ev = e_s4[r * 33 + e4];
            acc[r] = fmaf(wv.x, ev.x, acc[r]);
            acc[r] = fmaf(wv.y, ev.y, acc[r]);
            acc[r] = fmaf(wv.z, ev.z, acc[r]);
            acc[r] = fmaf(wv.w, ev.w, acc[r]);
        }
    }
    const int g = g0 + c;
    const float bias = bih[g] + bhh[g];
    #pragma unroll
    for (int r = 0; r < 32; ++r)
        g_xg[(size_t)(rowbase + r) * G4_ + g] = acc[r] + bias;
}

// =================== K2: persistent LSTM recurrence ========================
// monotonic acquire/release grid barrier (counter zeroed by zero_kernel)
__device__ __forceinline__ void grid_barrier(unsigned target, unsigned* bar) {
    __syncthreads();
    if (threadIdx.x == 0) {
        asm volatile("red.release.gpu.global.add.u32 [%0], %1;" :: "l"(bar), "r"(1u) : "memory");
        unsigned v;
        do {
            asm volatile("ld.acquire.gpu.global.u32 %0, [%1];" : "=r"(v) : "l"(bar) : "memory");
        } while (v < target);
    }
    __syncthreads();
}

__device__ __forceinline__ float fast_sig(float v)  { return 1.f / (1.f + __expf(-v)); }
__device__ __forceinline__ float fast_tanh(float v) {
    float e = __expf(-2.f * fabsf(v));
    float t = (1.f - e) / (1.f + e);
    return copysignf(t, v);
}

// 128 CTAs x 256 threads. CTA owns hidden units u0,u0+1 (8 gate rows).
// Compute phase: warp = k-slice (32 of 256), lanes = batch; each thread does
// partials for all 8 rows (h float4 reused 8x from regs). Smem reduction over
// the 8 k-slices, then elementwise cell.
__global__ void __launch_bounds__(256, 1) rec_kernel(
    const float* __restrict__ Whh_enc, const float* __restrict__ Whh_dec)
{
    extern __shared__ float smf[];
    float4* w_s4   = (float4*)smf;            // 8 rows x 64 f4      (8 KB)
    float4* h_s4   = w_s4 + 512;              // 32 x 65 f4 padded   (33.25 KB)
    float*  red_s  = (float*)(h_s4 + 32 * 65);// 8 slices x 8 rows x 32 b (8 KB)
    float*  gates_s= red_s + 2048;            // 8 x 32
    float*  c_s    = gates_s + 256;           // 64

    unsigned* bar;
    {  // generic address of the barrier counter
        bar = &g_bar_count;
    }

    const int tid = threadIdx.x;
    const int u0  = blockIdx.x * 2;
    const int s   = tid >> 5;        // warp k-slice 0..7
    const int b   = tid & 31;        // batch lane
    // reduction/xg mapping: row r (gate=r>>1, unit=r&1), batch br
    const int r   = tid >> 5;
    const int br  = tid & 31;
    const int grow = (r >> 1) * H_ + u0 + (r & 1);

    // load encoder Whh rows (8 rows x 256 fp32 = 512 float4)
    {
        const float4* W4 = (const float4*)Whh_enc;
        #pragma unroll
        for (int i = 0; i < 2; ++i) {
            int fi = tid + i * 256;
            int rr = fi >> 6, k4 = fi & 63;
            int gg = (rr >> 1) * H_ + u0 + (rr & 1);
            w_s4[rr * 64 + k4] = W4[(size_t)gg * 64 + k4];
        }
    }
    // init h buffer 0 (layout [b][u]) and c
    if (tid < 64) {
        int ul2 = tid >> 5, b2 = tid & 31;
        g_h[b2 * H_ + u0 + ul2] = 0.f;
        c_s[tid] = 0.f;
    }
    unsigned tgt = NCTA_REC;
    grid_barrier(tgt, bar); tgt += NCTA_REC;

    const float4* g_h4 = (const float4*)g_h;

    for (int step = 0; step < S_ + T_; ++step) {
        const bool dec = (step >= S_);
        const int  t   = dec ? step - S_ : step;
        const int  rdo4 = (step & 1) * 2048;            // read buffer (float4 idx)
        const int  wro  = ((step + 1) & 1) * (B_ * H_); // write buffer (float idx)

        // prefetch xg (independent of h; hides DRAM latency)
        const float* xg = g_xg + (dec ? (size_t)(B_ * S_) * G4_ : 0);
        float xg_v = __ldg(&xg[(size_t)(br * S_ + t) * G4_ + grow]);

        // pull full h into smem: [b][u] coalesced float4 copy
        #pragma unroll
        for (int i = 0; i < 8; ++i) {
            int fi = tid + i * 256;                 // 0..2047
            int bb = fi >> 6, k4 = fi & 63;
            float4 hv = __ldcg(&g_h4[rdo4 + fi]);
            h_s4[bb * 65 + k4] = hv;
        }
        __syncthreads();

        // split-k partials: 8 rows x this warp's 32-k slice
        float acc[8];
        #pragma unroll
        for (int rr = 0; rr < 8; ++rr) acc[rr] = 0.f;
        #pragma unroll
        for (int j4 = 0; j4 < 8; ++j4) {
            float4 hv = h_s4[b * 65 + s * 8 + j4];       // conflict-free
            #pragma unroll
            for (int rr = 0; rr < 8; ++rr) {
                float4 wv = w_s4[rr * 64 + s * 8 + j4];  // warp broadcast
                acc[rr] = fmaf(wv.x, hv.x, acc[rr]);
                acc[rr] = fmaf(wv.y, hv.y, acc[rr]);
                acc[rr] = fmaf(wv.z, hv.z, acc[rr]);
                acc[rr] = fmaf(wv.w, hv.w, acc[rr]);
            }
        }
        #pragma unroll
        for (int rr = 0; rr < 8; ++rr)
            red_s[(s * 8 + rr) * 32 + b] = acc[rr];
        __syncthreads();

        // reduce 8 k-slices + xg  -> gate preactivation
        {
            float sum = xg_v;
            #pragma unroll
            for (int ss = 0; ss < 8; ++ss)
                sum += red_s[(ss * 8 + r) * 32 + br];
            gates_s[r * 32 + br] = sum;
        }
        __syncthreads();

        // elementwise LSTM cell for this CTA's 2 units x 32 batches
        if (tid < 64) {
            int ul2 = tid >> 5, b2 = tid & 31;
            float iv = fast_sig (gates_s[(0 + ul2) * 32 + b2]);
            float fv = fast_sig (gates_s[(2 + ul2) * 32 + b2]);
            float gv = fast_tanh(gates_s[(4 + ul2) * 32 + b2]);
            float ov = fast_sig (gates_s[(6 + ul2) * 32 + b2]);
            float cc = fv * c_s[tid] + iv * gv;
            c_s[tid] = cc;
            float hh = ov * fast_tanh(cc);
            g_h[wro + b2 * H_ + u0 + ul2] = hh;
            if (dec) g_ah[(size_t)(b2 * T_ + t) * H_ + u0 + ul2] = __float2half(hh);
        }
        grid_barrier(tgt, bar); tgt += NCTA_REC;

        if (step == S_ - 1) {   // switch to decoder weights
            const float4* W4 = (const float4*)Whh_dec;
            #pragma unroll
            for (int i = 0; i < 2; ++i) {
                int fi = tid + i * 256;
                int rr = fi >> 6, k4 = fi & 63;
                int gg = (rr >> 1) * H_ + u0 + (rr & 1);
                w_s4[rr * 64 + k4] = W4[(size_t)gg * 64 + k4];
            }
            __syncthreads();
        }
    }
}

// =================== K3: output projection (fp16 mma.sync) =================
#define PROJ_SMEM (2 * 32768)

__device__ __forceinline__ void ldm_x4(uint32_t& r0, uint32_t& r1, uint32_t& r2, uint32_t& r3,
                                       uint32_t addr) {
    asm volatile("ldmatrix.sync.aligned.m8n8.x4.shared.b16 {%0,%1,%2,%3}, [%4];"
                 : "=r"(r0), "=r"(r1), "=r"(r2), "=r"(r3) : "r"(addr));
}
__device__ __forceinline__ void ldm_x2(uint32_t& r0, uint32_t& r1, uint32_t addr) {
    asm volatile("ldmatrix.sync.aligned.m8n8.x2.shared.b16 {%0,%1}, [%2];"
                 : "=r"(r0), "=r"(r1) : "r"(addr));
}
__device__ __forceinline__ void mma16816(float* d, const uint32_t* a, const uint32_t* b) {
    asm volatile(
        "mma.sync.aligned.m16n8k16.row.col.f32.f16.f16.f32 "
        "{%0,%1,%2,%3}, {%4,%5,%6,%7}, {%8,%9}, {%0,%1,%2,%3};"
        : "+f"(d[0]), "+f"(d[1]), "+f"(d[2]), "+f"(d[3])
        : "r"(a[0]), "r"(a[1]), "r"(a[2]), "r"(a[3]), "r"(b[0]), "r"(b[1]));
}

__global__ void __launch_bounds__(256, 2) proj_kernel(const float* __restrict__ bout,
                                                      float* __restrict__ out)
{
    extern __shared__ char smem[];
    const uint32_t sbase = smem_to_u32(smem);
    const int tid  = threadIdx.x;
    const int lane = tid & 31;
    const int w    = tid >> 5;
    const int wm   = w >> 2;
    const int wn   = w & 3;
    const int m0   = blockIdx.x * 128;
    const int n0   = blockIdx.y * 128;

    auto issue_chunk = [&](int c, int s) {
        const uint32_t abuf = sbase + s * 32768;
        const uint32_t bbuf = abuf + 16384;
        const __half* Ag = g_ah + (size_t)m0 * H_ + c * 64;
        const __half* Bg = g_bh + (size_t)n0 * H_ + c * 64;
        #pragma unroll
        for (int j = 0; j < 4; ++j) {
            int fi = tid + j * 256;
            int row = fi >> 3, c8 = fi & 7;
            uint32_t soff = SWZ128((uint32_t)(row * 128 + c8 * 16));
            const void* ga = (const char*)(Ag + (size_t)row * H_ + c8 * 8);
            const void* gb = (const char*)(Bg + (size_t)row * H_ + c8 * 8);
            asm volatile("cp.async.cg.shared.global [%0], [%1], 16;" :: "r"(abuf + soff), "l"(ga));
            asm volatile("cp.async.cg.shared.global [%0], [%1], 16;" :: "r"(bbuf + soff), "l"(gb));
        }
        asm volatile("cp.async.commit_group;" ::: "memory");
    };

    float acc[4][4][4];
    #pragma unroll
    for (int i = 0; i < 4; ++i)
        #pragma unroll
        for (int j = 0; j < 4; ++j)
            #pragma unroll
            for (int k = 0; k < 4; ++k) acc[i][j][k] = 0.f;

    issue_chunk(0, 0);
    issue_chunk(1, 1);

    const int l16 = lane & 15;
    #pragma unroll 1
    for (int c = 0; c < 4; ++c) {
        if (c < 3) asm volatile("cp.async.wait_group 1;" ::: "memory");
        else       asm volatile("cp.async.wait_group 0;" ::: "memory");
        __syncthreads();

        const uint32_t abuf = sbase + (c & 1) * 32768;
        const uint32_t bbuf = abuf + 16384;

        #pragma unroll
        for (int ks = 0; ks < 4; ++ks) {
            uint32_t a[4][4], b[4][2];
            #pragma unroll
            for (int mi = 0; mi < 4; ++mi) {
                int row = wm * 64 + mi * 16 + l16;
                uint32_t off = (uint32_t)(row * 128 + ks * 32 + (lane >> 4) * 16);
                ldm_x4(a[mi][0], a[mi][1], a[mi][2], a[mi][3], abuf + SWZ128(off));
            }
            #pragma unroll
            for (int bi = 0; bi < 4; ++bi) {
                int row = wn * 32 + bi * 8 + (l16 & 7);
                uint32_t off = (uint32_t)(row * 128 + ks * 32 + (l16 >> 3) * 16);
                ldm_x2(b[bi][0], b[bi][1], bbuf + SWZ128(off));
            }
            #pragma unroll
            for (int mi = 0; mi < 4; ++mi)
                #pragma unroll
                for (int bi = 0; bi < 4; ++bi)
                    mma16816(acc[mi][bi], a[mi], b[bi]);
        }
        __syncthreads();
        if (c + 2 < 4) issue_chunk(c + 2, c & 1);
    }

    #pragma unroll
    for (int bi = 0; bi < 4; ++bi) {
        const int col = n0 + wn * 32 + bi * 8 + (lane & 3) * 2;
        const float2 bb = *(const float2*)(bout + col);
        #pragma unroll
        for (int mi = 0; mi < 4; ++mi) {
            const int row = m0 + wm * 64 + mi * 16 + (lane >> 2);
            float2 v0 = make_float2(acc[mi][bi][0] + bb.x, acc[mi][bi][1] + bb.y);
            float2 v1 = make_float2(acc[mi][bi][2] + bb.x, acc[mi][bi][3] + bb.y);
            *(float2*)(out + (size_t)row * V_ + col) = v0;
            *(float2*)(out + (size_t)(row + 8) * V_ + col) = v1;
        }
    }
}

// ============================= launch ======================================
extern "C" void kernel_launch(void* const* d_in, const int* in_sizes, int n_in,
                              void* d_out, int out_size) {
    const int*   x        = (const int*)d_in[0];
    const int*   y        = (const int*)d_in[1];
    const float* enc_emb  = (const float*)d_in[2];
    const float* dec_emb  = (const float*)d_in[3];
    const float* Wih_enc  = (const float*)d_in[4];
    const float* Whh_enc  = (const float*)d_in[5];
    const float* bih_enc  = (const float*)d_in[6];
    const float* bhh_enc  = (const float*)d_in[7];
    const float* Wih_dec  = (const float*)d_in[8];
    const float* Whh_dec  = (const float*)d_in[9];
    const float* bih_dec  = (const float*)d_in[10];
    const float* bhh_dec  = (const float*)d_in[11];
    const float* Wout     = (const float*)d_in[12];
    const float* bout     = (const float*)d_in[13];
    float*       out      = (float*)d_out;

    const int XG_SMEM  = (256 * 132 + 32 * 132) * 4;
    const int REC_SMEM = (512 + 32 * 65) * 16 + (2048 + 256 + 64) * 4;  // 50944

    cudaFuncSetAttribute(xg_kernel,  cudaFuncAttributeMaxDynamicSharedMemorySize, XG_SMEM);
    cudaFuncSetAttribute(rec_kernel, cudaFuncAttributeMaxDynamicSharedMemorySize, REC_SMEM);
    cudaFuncSetAttribute(proj_kernel, cudaFuncAttributeMaxDynamicSharedMemorySize, PROJ_SMEM);

    __half *bh;
    cudaGetSymbolAddress((void**)&bh, g_bh);

    zero_kernel<<<1, 1>>>();
    tohalf_kernel<<<(V_ * H_ / 4 + 255) / 256, 256>>>(Wout, bh, V_ * H_ / 4);

    xg_kernel<<<1024, 256, XG_SMEM>>>(x, y, enc_emb, dec_emb,
                                      Wih_enc, bih_enc, bhh_enc,
                                      Wih_dec, bih_dec, bhh_dec);
    rec_kernel<<<NCTA_REC, 256, REC_SMEM>>>(Whh_enc, Whh_dec);

    proj_kernel<<<dim3(32, V_ / 128), 256, PROJ_SMEM>>>(bout, out);
}

// round 6
// speedup vs baseline: 2.7636x; 1.1021x over previous
#include <cuda_runtime.h>
#include <cuda_fp16.h>
#include <cstdint>

#define B_   32
#define S_   128
#define T_   128
#define E_   128
#define H_   256
#define G4_  1024
#define V_   32000

// ---------------- scratch (device globals; no allocation) ----------------
__device__ float   g_xg[(size_t)(2 * B_ * S_) * G4_];   // [8192][1024] enc then dec
// fp16 operands for tensor-core projection
__device__ __half  g_ah[(size_t)B_ * T_ * H_];          // dec_out fp16 [4096][256]
__device__ __half  g_bh[(size_t)V_ * H_];               // W_out  fp16 [32000][256]

#define SWZ128(off) ((off) ^ (((off) >> 3) & 0x70))

__device__ __forceinline__ uint32_t smem_to_u32(const void* p) {
    uint32_t a;
    asm("{ .reg .u64 t; cvta.to.shared.u64 t, %1; cvt.u32.u64 %0, t; }" : "=r"(a) : "l"(p));
    return a;
}

// =================== K0: fp32 -> fp16 convert ==============================
__global__ void __launch_bounds__(256) tohalf_kernel(const float* __restrict__ src,
                                                     __half* __restrict__ dst, int n4) {
    int i = blockIdx.x * 256 + threadIdx.x;
    if (i >= n4) return;
    float4 v = ((const float4*)src)[i];
    ((__half2*)dst)[2 * i]     = __floats2half2_rn(v.x, v.y);
    ((__half2*)dst)[2 * i + 1] = __floats2half2_rn(v.z, v.w);
}

// =================== K1: embedding gather + input-gate GEMM ===============
__global__ void __launch_bounds__(256, 1) xg_kernel(
    const int* __restrict__ x, const int* __restrict__ y,
    const float* __restrict__ enc_emb, const float* __restrict__ dec_emb,
    const float* __restrict__ Wih_enc, const float* __restrict__ bih_enc,
    const float* __restrict__ bhh_enc,
    const float* __restrict__ Wih_dec, const float* __restrict__ bih_dec,
    const float* __restrict__ bhh_dec)
{
    extern __shared__ float sm[];
    float4* w_s4 = (float4*)sm;                    // [256][33] float4
    float4* e_s4 = (float4*)(sm + 256 * 132);      // [32][33]
    __shared__ int tok_s[32];

    const int tid = threadIdx.x;
    const int rt = blockIdx.x >> 2;
    const int ct = blockIdx.x & 3;
    const int rowbase = rt * 32;
    const bool enc = rowbase < (B_ * S_);

    const float* Wih = enc ? Wih_enc : Wih_dec;
    const float* emb = enc ? enc_emb : dec_emb;
    const float* bih = enc ? bih_enc : bih_dec;
    const float* bhh = enc ? bhh_enc : bhh_dec;
    const int*  toks = enc ? x : y;
    const int   rb   = enc ? rowbase : rowbase - B_ * S_;

    const int g0 = ct * 256;
    const float4* W4 = (const float4*)(Wih + (size_t)g0 * E_);
    #pragma unroll
    for (int i = 0; i < 32; ++i) {
        int fi = tid + i * 256;
        int gr = fi >> 5, e4 = fi & 31;
        w_s4[gr * 33 + e4] = W4[gr * 32 + e4];
    }
    if (tid < 32) tok_s[tid] = toks[rb + tid];
    __syncthreads();

    #pragma unroll
    for (int i = 0; i < 4; ++i) {
        int fi = tid + i * 256;
        int r = fi >> 5, e4 = fi & 31;
        e_s4[r * 33 + e4] = ((const float4*)emb)[(size_t)tok_s[r] * 32 + e4];
    }
    __syncthreads();

    float acc[32];
    #pragma unroll
    for (int r = 0; r < 32; ++r) acc[r] = 0.f;

    const int c = tid;
    #pragma unroll 8
    for (int e4 = 0; e4 < 32; ++e4) {
        float4 wv = w_s4[c * 33 + e4];
        #pragma unroll
        for (int r = 0; r < 32; ++r) {
            float4 ev = e_s4[r * 33 + e4];
            acc[r] = fmaf(wv.x, ev.x, acc[r]);
            acc[r] = fmaf(wv.y, ev.y, acc[r]);
            acc[r] = fmaf(wv.z, ev.z, acc[r]);
            acc[r] = fmaf(wv.w, ev.w, acc[r]);
        }
    }
    const int g = g0 + c;
    const float bias = bih[g] + bhh[g];
    #pragma unroll
    for (int r = 0; r < 32; ++r)
        g_xg[(size_t)(rowbase + r) * G4_ + g] = acc[r] + bias;
}

// =================== K2: clustered LSTM recurrence ========================
// 16 clusters x 8 CTAs. Cluster owns 2 batches; CTA rank owns 32 hidden units
// (128 gate rows). Whh rows live in REGISTERS (thread = 4 rows x 32-k slice).
// h exchanged via DSMEM st.shared::cluster + barrier.cluster. No global sync.
__device__ __forceinline__ float fast_sig(float v)  { return 1.f / (1.f + __expf(-v)); }
__device__ __forceinline__ float fast_tanh(float v) {
    float e = __expf(-2.f * fabsf(v));
    float t = (1.f - e) / (1.f + e);
    return copysignf(t, v);
}

__device__ __forceinline__ void load_w(float (&w)[4][32], const float* __restrict__ Whh,
                                       int rg, int s, int u0) {
    #pragma unroll
    for (int rr = 0; rr < 4; ++rr) {
        int lr = rg * 4 + rr;                         // local row 0..127
        int grow = (lr >> 5) * H_ + u0 + (lr & 31);   // gate*256 + unit
        const float4* src = (const float4*)(Whh + (size_t)grow * H_ + s * 32);
        #pragma unroll
        for (int q = 0; q < 8; ++q) {
            float4 v = src[q];
            w[rr][q * 4 + 0] = v.x; w[rr][q * 4 + 1] = v.y;
            w[rr][q * 4 + 2] = v.z; w[rr][q * 4 + 3] = v.w;
        }
    }
}

#define ST_CLUSTER_F32(localAddr, rnk, val) \
    asm volatile("{ .reg .b32 ra; mapa.shared::cluster.u32 ra, %0, %1; " \
                 "st.shared::cluster.f32 [ra], %2; }" \
                 :: "r"(localAddr), "r"(rnk), "f"(val) : "memory")

__global__ void __launch_bounds__(256, 1) __cluster_dims__(8, 1, 1)
rec_kernel(const float* __restrict__ Whh_enc, const float* __restrict__ Whh_dec)
{
    __shared__ float2 h_s[2][256];     // [buf][k] = (batch0, batch1) of this cluster
    __shared__ float2 red_s[8][128];   // [k-slice][local row] partial sums

    const int tid  = threadIdx.x;
    const int s    = tid >> 5;         // warp = k-slice (32 k)
    const int rg   = tid & 31;         // lane = row-group (4 rows)
    const int rank = blockIdx.x & 7;
    const int u0   = rank * 32;
    const int bglob0 = (blockIdx.x >> 3) * 2;

    // reducer identity (tid < 64): unit uu, cluster-batch bb
    const int uu = tid & 31;
    const int bb = (tid >> 5) & 1;
    const int bglob = bglob0 + bb;

    float w[4][32];
    load_w(w, Whh_enc, rg, s, u0);

    // init h buffer 0 to zeros; c state lives in reducer registers
    h_s[0][tid & 255] = make_float2(0.f, 0.f);
    float c_reg = 0.f;
    __syncthreads();

    const uint32_t h_addr_base[2] = {
        smem_to_u32(&h_s[0][u0 + uu]) + (uint32_t)bb * 4,
        smem_to_u32(&h_s[1][u0 + uu]) + (uint32_t)bb * 4
    };

    for (int step = 0; step < S_ + T_; ++step) {
        const bool dec = (step >= S_);
        const int  t   = dec ? step - S_ : step;
        const int  buf = step & 1;

        // prefetch xg for this step's cell update (L2; latency hidden by compute)
        float xgv[4];
        if (tid < 64) {
            const float* xg = g_xg + (dec ? (size_t)(B_ * S_) * G4_ : 0)
                            + (size_t)(bglob * S_ + t) * G4_ + u0 + uu;
            #pragma unroll
            for (int g = 0; g < 4; ++g) xgv[g] = __ldcg(&xg[g * H_]);
        }

        // split-k compute: 4 rows x 32 k x 2 batches, W in regs, h broadcast
        const float2* hb = h_s[buf];
        float2 acc[4];
        #pragma unroll
        for (int rr = 0; rr < 4; ++rr) acc[rr] = make_float2(0.f, 0.f);
        #pragma unroll
        for (int kk = 0; kk < 32; ++kk) {
            float2 h2 = hb[s * 32 + kk];              // warp broadcast
            #pragma unroll
            for (int rr = 0; rr < 4; ++rr) {
                acc[rr].x = fmaf(w[rr][kk], h2.x, acc[rr].x);
                acc[rr].y = fmaf(w[rr][kk], h2.y, acc[rr].y);
            }
        }
        #pragma unroll
        for (int rr = 0; rr < 4; ++rr)
            red_s[s][rg * 4 + rr] = acc[rr];
        __syncthreads();

        // reduce 8 slices + xg, apply LSTM cell, broadcast h to cluster
        if (tid < 64) {
            float pre[4];
            #pragma unroll
            for (int g = 0; g < 4; ++g) {
                float sum = xgv[g];
                #pragma unroll
                for (int ss = 0; ss < 8; ++ss) {
                    float2 v = red_s[ss][g * 32 + uu];
                    sum += bb ? v.y : v.x;
                }
                pre[g] = sum;
            }
            float iv = fast_sig(pre[0]);
            float fv = fast_sig(pre[1]);
            float gv = fast_tanh(pre[2]);
            float ov = fast_sig(pre[3]);
            c_reg = fv * c_reg + iv * gv;
            float hh = ov * fast_tanh(c_reg);

            const uint32_t dst = h_addr_base[buf ^ 1];
            #pragma unroll
            for (int p = 0; p < 8; ++p) ST_CLUSTER_F32(dst, p, hh);

            if (dec) g_ah[(size_t)(bglob * T_ + t) * H_ + u0 + uu] = __float2half(hh);
        }

        // cluster barrier (release DSMEM stores / acquire for next step)
        asm volatile("barrier.cluster.arrive.aligned;" ::: "memory");
        if (step == S_ - 1) load_w(w, Whh_dec, rg, s, u0);   // overlap with skew
        asm volatile("barrier.cluster.wait.aligned;" ::: "memory");
    }
}

// =================== K3: output projection (fp16 mma.sync) =================
#define PROJ_SMEM (2 * 32768)

__device__ __forceinline__ void ldm_x4(uint32_t& r0, uint32_t& r1, uint32_t& r2, uint32_t& r3,
                                       uint32_t addr) {
    asm volatile("ldmatrix.sync.aligned.m8n8.x4.shared.b16 {%0,%1,%2,%3}, [%4];"
                 : "=r"(r0), "=r"(r1), "=r"(r2), "=r"(r3) : "r"(addr));
}
__device__ __forceinline__ void ldm_x2(uint32_t& r0, uint32_t& r1, uint32_t addr) {
    asm volatile("ldmatrix.sync.aligned.m8n8.x2.shared.b16 {%0,%1}, [%2];"
                 : "=r"(r0), "=r"(r1) : "r"(addr));
}
__device__ __forceinline__ void mma16816(float* d, const uint32_t* a, const uint32_t* b) {
    asm volatile(
        "mma.sync.aligned.m16n8k16.row.col.f32.f16.f16.f32 "
        "{%0,%1,%2,%3}, {%4,%5,%6,%7}, {%8,%9}, {%0,%1,%2,%3};"
        : "+f"(d[0]), "+f"(d[1]), "+f"(d[2]), "+f"(d[3])
        : "r"(a[0]), "r"(a[1]), "r"(a[2]), "r"(a[3]), "r"(b[0]), "r"(b[1]));
}

__global__ void __launch_bounds__(256, 2) proj_kernel(const float* __restrict__ bout,
                                                      float* __restrict__ out)
{
    extern __shared__ char smem[];
    const uint32_t sbase = smem_to_u32(smem);
    const int tid  = threadIdx.x;
    const int lane = tid & 31;
    const int w    = tid >> 5;
    const int wm   = w >> 2;
    const int wn   = w & 3;
    const int m0   = blockIdx.x * 128;
    const int n0   = blockIdx.y * 128;

    auto issue_chunk = [&](int c, int s) {
        const uint32_t abuf = sbase + s * 32768;
        const uint32_t bbuf = abuf + 16384;
        const __half* Ag = g_ah + (size_t)m0 * H_ + c * 64;
        const __half* Bg = g_bh + (size_t)n0 * H_ + c * 64;
        #pragma unroll
        for (int j = 0; j < 4; ++j) {
            int fi = tid + j * 256;
            int row = fi >> 3, c8 = fi & 7;
            uint32_t soff = SWZ128((uint32_t)(row * 128 + c8 * 16));
            const void* ga = (const char*)(Ag + (size_t)row * H_ + c8 * 8);
            const void* gb = (const char*)(Bg + (size_t)row * H_ + c8 * 8);
            asm volatile("cp.async.cg.shared.global [%0], [%1], 16;" :: "r"(abuf + soff), "l"(ga));
            asm volatile("cp.async.cg.shared.global [%0], [%1], 16;" :: "r"(bbuf + soff), "l"(gb));
        }
        asm volatile("cp.async.commit_group;" ::: "memory");
    };

    float acc[4][4][4];
    #pragma unroll
    for (int i = 0; i < 4; ++i)
        #pragma unroll
        for (int j = 0; j < 4; ++j)
            #pragma unroll
            for (int k = 0; k < 4; ++k) acc[i][j][k] = 0.f;

    issue_chunk(0, 0);
    issue_chunk(1, 1);

    const int l16 = lane & 15;
    #pragma unroll 1
    for (int c = 0; c < 4; ++c) {
        if (c < 3) asm volatile("cp.async.wait_group 1;" ::: "memory");
        else       asm volatile("cp.async.wait_group 0;" ::: "memory");
        __syncthreads();

        const uint32_t abuf = sbase + (c & 1) * 32768;
        const uint32_t bbuf = abuf + 16384;

        #pragma unroll
        for (int ks = 0; ks < 4; ++ks) {
            uint32_t a[4][4], b[4][2];
            #pragma unroll
            for (int mi = 0; mi < 4; ++mi) {
                int row = wm * 64 + mi * 16 + l16;
                uint32_t off = (uint32_t)(row * 128 + ks * 32 + (lane >> 4) * 16);
                ldm_x4(a[mi][0], a[mi][1], a[mi][2], a[mi][3], abuf + SWZ128(off));
            }
            #pragma unroll
            for (int bi = 0; bi < 4; ++bi) {
                int row = wn * 32 + bi * 8 + (l16 & 7);
                uint32_t off = (uint32_t)(row * 128 + ks * 32 + (l16 >> 3) * 16);
                ldm_x2(b[bi][0], b[bi][1], bbuf + SWZ128(off));
            }
            #pragma unroll
            for (int mi = 0; mi < 4; ++mi)
                #pragma unroll
                for (int bi = 0; bi < 4; ++bi)
                    mma16816(acc[mi][bi], a[mi], b[bi]);
        }
        __syncthreads();
        if (c + 2 < 4) issue_chunk(c + 2, c & 1);
    }

    #pragma unroll
    for (int bi = 0; bi < 4; ++bi) {
        const int col = n0 + wn * 32 + bi * 8 + (lane & 3) * 2;
        const float2 bb = *(const float2*)(bout + col);
        #pragma unroll
        for (int mi = 0; mi < 4; ++mi) {
            const int row = m0 + wm * 64 + mi * 16 + (lane >> 2);
            float2 v0 = make_float2(acc[mi][bi][0] + bb.x, acc[mi][bi][1] + bb.y);
            float2 v1 = make_float2(acc[mi][bi][2] + bb.x, acc[mi][bi][3] + bb.y);
            *(float2*)(out + (size_t)row * V_ + col) = v0;
            *(float2*)(out + (size_t)(row + 8) * V_ + col) = v1;
        }
    }
}

// ============================= launch ======================================
extern "C" void kernel_launch(void* const* d_in, const int* in_sizes, int n_in,
                              void* d_out, int out_size) {
    const int*   x        = (const int*)d_in[0];
    const int*   y        = (const int*)d_in[1];
    const float* enc_emb  = (const float*)d_in[2];
    const float* dec_emb  = (const float*)d_in[3];
    const float* Wih_enc  = (const float*)d_in[4];
    const float* Whh_enc  = (const float*)d_in[5];
    const float* bih_enc  = (const float*)d_in[6];
    const float* bhh_enc  = (const float*)d_in[7];
    const float* Wih_dec  = (const float*)d_in[8];
    const float* Whh_dec  = (const float*)d_in[9];
    const float* bih_dec  = (const float*)d_in[10];
    const float* bhh_dec  = (const float*)d_in[11];
    const float* Wout     = (const float*)d_in[12];
    const float* bout     = (const float*)d_in[13];
    float*       out      = (float*)d_out;

    const int XG_SMEM = (256 * 132 + 32 * 132) * 4;

    cudaFuncSetAttribute(xg_kernel,  cudaFuncAttributeMaxDynamicSharedMemorySize, XG_SMEM);
    cudaFuncSetAttribute(proj_kernel, cudaFuncAttributeMaxDynamicSharedMemorySize, PROJ_SMEM);

    __half *bh;
    cudaGetSymbolAddress((void**)&bh, g_bh);

    tohalf_kernel<<<(V_ * H_ / 4 + 255) / 256, 256>>>(Wout, bh, V_ * H_ / 4);

    xg_kernel<<<1024, 256, XG_SMEM>>>(x, y, enc_emb, dec_emb,
                                      Wih_enc, bih_enc, bhh_enc,
                                      Wih_dec, bih_dec, bhh_dec);

    rec_kernel<<<128, 256>>>(Whh_enc, Whh_dec);

    proj_kernel<<<dim3(32, V_ / 128), 256, PROJ_SMEM>>>(bout, out);
}

// round 7
// speedup vs baseline: 2.8612x; 1.0353x over previous
#include <cuda_runtime.h>
#include <cuda_fp16.h>
#include <cstdint>

#define B_   32
#define S_   128
#define T_   128
#define E_   128
#define H_   256
#define G4_  1024
#define V_   32000

typedef unsigned long long ull;

// ---------------- scratch (device globals; no allocation) ----------------
__device__ float   g_xg[(size_t)(2 * B_ * S_) * G4_];   // [8192][1024] enc then dec
// fp16 operands for tensor-core projection
__device__ __half  g_ah[(size_t)B_ * T_ * H_];          // dec_out fp16 [4096][256]
__device__ __half  g_bh[(size_t)V_ * H_];               // W_out  fp16 [32000][256]

#define SWZ128(off) ((off) ^ (((off) >> 3) & 0x70))

__device__ __forceinline__ uint32_t smem_to_u32(const void* p) {
    uint32_t a;
    asm("{ .reg .u64 t; cvta.to.shared.u64 t, %1; cvt.u32.u64 %0, t; }" : "=r"(a) : "l"(p));
    return a;
}

// =================== K0: fp32 -> fp16 convert ==============================
__global__ void __launch_bounds__(256) tohalf_kernel(const float* __restrict__ src,
                                                     __half* __restrict__ dst, int n4) {
    int i = blockIdx.x * 256 + threadIdx.x;
    if (i >= n4) return;
    float4 v = ((const float4*)src)[i];
    ((__half2*)dst)[2 * i]     = __floats2half2_rn(v.x, v.y);
    ((__half2*)dst)[2 * i + 1] = __floats2half2_rn(v.z, v.w);
}

// =================== K1: embedding gather + input-gate GEMM ===============
__global__ void __launch_bounds__(256, 1) xg_kernel(
    const int* __restrict__ x, const int* __restrict__ y,
    const float* __restrict__ enc_emb, const float* __restrict__ dec_emb,
    const float* __restrict__ Wih_enc, const float* __restrict__ bih_enc,
    const float* __restrict__ bhh_enc,
    const float* __restrict__ Wih_dec, const float* __restrict__ bih_dec,
    const float* __restrict__ bhh_dec)
{
    extern __shared__ float sm[];
    float4* w_s4 = (float4*)sm;                    // [256][33] float4
    float4* e_s4 = (float4*)(sm + 256 * 132);      // [32][33]
    __shared__ int tok_s[32];

    const int tid = threadIdx.x;
    const int rt = blockIdx.x >> 2;
    const int ct = blockIdx.x & 3;
    const int rowbase = rt * 32;
    const bool enc = rowbase < (B_ * S_);

    const float* Wih = enc ? Wih_enc : Wih_dec;
    const float* emb = enc ? enc_emb : dec_emb;
    const float* bih = enc ? bih_enc : bih_dec;
    const float* bhh = enc ? bhh_enc : bhh_dec;
    const int*  toks = enc ? x : y;
    const int   rb   = enc ? rowbase : rowbase - B_ * S_;

    const int g0 = ct * 256;
    const float4* W4 = (const float4*)(Wih + (size_t)g0 * E_);
    #pragma unroll
    for (int i = 0; i < 32; ++i) {
        int fi = tid + i * 256;
        int gr = fi >> 5, e4 = fi & 31;
        w_s4[gr * 33 + e4] = W4[gr * 32 + e4];
    }
    if (tid < 32) tok_s[tid] = toks[rb + tid];
    __syncthreads();

    #pragma unroll
    for (int i = 0; i < 4; ++i) {
        int fi = tid + i * 256;
        int r = fi >> 5, e4 = fi & 31;
        e_s4[r * 33 + e4] = ((const float4*)emb)[(size_t)tok_s[r] * 32 + e4];
    }
    __syncthreads();

    float acc[32];
    #pragma unroll
    for (int r = 0; r < 32; ++r) acc[r] = 0.f;

    const int c = tid;
    #pragma unroll 8
    for (int e4 = 0; e4 < 32; ++e4) {
        float4 wv = w_s4[c * 33 + e4];
        #pragma unroll
        for (int r = 0; r < 32; ++r) {
            float4 ev = e_s4[r * 33 + e4];
            acc[r] = fmaf(wv.x, ev.x, acc[r]);
            acc[r] = fmaf(wv.y, ev.y, acc[r]);
            acc[r] = fmaf(wv.z, ev.z, acc[r]);
            acc[r] = fmaf(wv.w, ev.w, acc[r]);
        }
    }
    const int g = g0 + c;
    const float bias = bih[g] + bhh[g];
    #pragma unroll
    for (int r = 0; r < 32; ++r)
        g_xg[(size_t)(rowbase + r) * G4_ + g] = acc[r] + bias;
}

// =================== K2: clustered LSTM recurrence (st.async) ==============
// 16 clusters x 8 CTAs; cluster owns 2 batches; CTA rank owns 32 units
// (128 gate rows). Whh packed row-pairs in REGISTERS, fma.rn.f32x2 compute.
// h exchange: st.async -> remote mbarrier tx-count. No cluster barrier in loop.
__device__ __forceinline__ float fast_sig(float v)  { return 1.f / (1.f + __expf(-v)); }
__device__ __forceinline__ float fast_tanh(float v) {
    float e = __expf(-2.f * fabsf(v));
    float t = (1.f - e) / (1.f + e);
    return copysignf(t, v);
}

#define MBARRIER_INIT(mbar, count) \
    asm volatile("mbarrier.init.shared.b64 [%0], %1;" :: "r"((uint32_t)(mbar)), "r"((uint32_t)(count)) : "memory")
#define MBARRIER_EXPECT_TX(mbar, tx) \
    asm volatile("mbarrier.arrive.expect_tx.shared.b64 _, [%0], %1;" :: "r"((uint32_t)(mbar)), "r"((uint32_t)(tx)) : "memory")
#define MBARRIER_WAIT_PARITY(mbar, parity) do {                                         \
    uint32_t _m = (uint32_t)(mbar); uint32_t _p = (uint32_t)(parity); uint32_t _d;      \
    asm volatile("{\n\t.reg .pred p;\n\t"                                               \
        "mbarrier.try_wait.parity.acquire.cta.shared::cta.b64 p, [%1], %2;\n\t"         \
        "selp.b32 %0, 1, 0, p;\n\t}" : "=r"(_d) : "r"(_m), "r"(_p) : "memory");         \
    if (!_d) {                                                                           \
        asm volatile("{\n\t.reg .pred P1;\n\t"                                          \
            "WL_%=:\n\t"                                                                \
            "mbarrier.try_wait.parity.acquire.cta.shared::cta.b64 P1, [%0], %1, 0x989680;\n\t" \
            "@P1 bra.uni WD_%=;\n\t"                                                    \
            "bra.uni WL_%=;\n\t"                                                        \
            "WD_%=:\n\t}" :: "r"(_m), "r"(_p) : "memory");                              \
    } } while (0)

// remote packed-8B store with tx-completion on the remote mbarrier
#define ST_ASYNC_B64(laddr, lmbar, rnk, val) \
    asm volatile("{ .reg .b32 ra, rb;\n\t" \
        "mapa.shared::cluster.u32 ra, %0, %2;\n\t" \
        "mapa.shared::cluster.u32 rb, %1, %2;\n\t" \
        "st.async.shared::cluster.mbarrier::complete_tx::bytes.b64 [ra], %3, [rb]; }" \
        :: "r"((uint32_t)(laddr)), "r"((uint32_t)(lmbar)), "r"((uint32_t)(rnk)), "l"(val) : "memory")

#define FMA2(d, a, b) asm("fma.rn.f32x2 %0, %1, %2, %0;" : "+l"(d) : "l"(a), "l"(b))

__device__ __forceinline__ void load_wp(ull (&wp)[2][32], const float* __restrict__ Whh,
                                        int rg, int s, int u0) {
    const int gate = rg >> 3;
    const int ub   = u0 + ((rg * 4) & 31);
    #pragma unroll
    for (int p = 0; p < 2; ++p) {
        const float4* r0 = (const float4*)(Whh + (size_t)(gate * H_ + ub + 2 * p) * H_ + s * 32);
        const float4* r1 = (const float4*)(Whh + (size_t)(gate * H_ + ub + 2 * p + 1) * H_ + s * 32);
        #pragma unroll
        for (int q = 0; q < 8; ++q) {
            float4 a = r0[q], b = r1[q];
            asm("mov.b64 %0, {%1,%2};" : "=l"(wp[p][q * 4 + 0]) : "f"(a.x), "f"(b.x));
            asm("mov.b64 %0, {%1,%2};" : "=l"(wp[p][q * 4 + 1]) : "f"(a.y), "f"(b.y));
            asm("mov.b64 %0, {%1,%2};" : "=l"(wp[p][q * 4 + 2]) : "f"(a.z), "f"(b.z));
            asm("mov.b64 %0, {%1,%2};" : "=l"(wp[p][q * 4 + 3]) : "f"(a.w), "f"(b.w));
        }
    }
}

__global__ void __launch_bounds__(256, 1) __cluster_dims__(8, 1, 1)
rec_kernel(const float* __restrict__ Whh_enc, const float* __restrict__ Whh_dec)
{
    __shared__ float4 h_s[2][256];     // [buf][unit] = (b0,b0,b1,b1)
    __shared__ float2 red_s[8][128];   // [k-slice][local row] = (b0,b1)
    __shared__ ull    mb[2];

    const int tid  = threadIdx.x;
    const int s    = tid >> 5;          // warp = k-slice (32 k)
    const int rg   = tid & 31;          // lane = row-group (4 rows)
    const int rank = blockIdx.x & 7;
    const int u0   = rank * 32;
    const int bglob0 = (blockIdx.x >> 3) * 2;

    // reducer identity (tid < 64)
    const int uu = tid & 31;
    const int bb = (tid >> 5) & 1;
    const int bglob = bglob0 + bb;

    const uint32_t mb_a[2] = { smem_to_u32(&mb[0]), smem_to_u32(&mb[1]) };
    const uint32_t hbase[2] = { smem_to_u32(&h_s[0][0]), smem_to_u32(&h_s[1][0]) };
    const uint32_t TX = 8 * 64 * 8;     // 4096 bytes per phase

    ull wp[2][32];
    load_wp(wp, Whh_enc, rg, s, u0);

    h_s[0][tid] = make_float4(0.f, 0.f, 0.f, 0.f);
    float c_reg = 0.f;
    if (tid == 0) {
        MBARRIER_INIT(mb_a[0], 1);
        MBARRIER_INIT(mb_a[1], 1);
        MBARRIER_EXPECT_TX(mb_a[1], TX);   // covers step-0 producers
    }
    // all CTAs: mbarriers + h_s[0] ready before any st.async
    asm volatile("barrier.cluster.arrive.aligned;" ::: "memory");
    asm volatile("barrier.cluster.wait.aligned;" ::: "memory");

    int ph[2] = {0, 0};

    for (int step = 0; step < S_ + T_; ++step) {
        const bool dec  = (step >= S_);
        const int  t    = dec ? step - S_ : step;
        const int  buf  = step & 1;
        const bool last = (step == S_ + T_ - 1);

        if (step > 0) {
            MBARRIER_WAIT_PARITY(mb_a[buf], ph[buf]);
            ph[buf] ^= 1;
            if (tid == 0 && !last) MBARRIER_EXPECT_TX(mb_a[buf ^ 1], TX);
        }

        // xg prefetch (reducers); consumed after the reduction
        float xgv[4];
        if (tid < 64) {
            const float* xg = g_xg + (dec ? (size_t)(B_ * S_) * G4_ : 0)
                            + (size_t)(bglob * S_ + t) * G4_ + u0 + uu;
            #pragma unroll
            for (int g = 0; g < 4; ++g) xgv[g] = __ldcg(&xg[g * H_]);
        }

        // split-k compute: fma.f32x2, W in regs, h warp-broadcast LDS.128
        ull acc2[2][2];
        #pragma unroll
        for (int p = 0; p < 2; ++p)
            #pragma unroll
            for (int b = 0; b < 2; ++b)
                asm("mov.b64 %0, {%1,%1};" : "=l"(acc2[p][b]) : "f"(0.f));
        const uint32_t hrow = hbase[buf] + (uint32_t)(s * 32) * 16;
        #pragma unroll
        for (int kk = 0; kk < 32; ++kk) {
            ull hb0, hb1;
            asm("ld.shared.v2.b64 {%0,%1}, [%2];" : "=l"(hb0), "=l"(hb1)
                : "r"(hrow + (uint32_t)kk * 16));
            FMA2(acc2[0][0], wp[0][kk], hb0);
            FMA2(acc2[0][1], wp[0][kk], hb1);
            FMA2(acc2[1][0], wp[1][kk], hb0);
            FMA2(acc2[1][1], wp[1][kk], hb1);
        }
        // unpack -> red_s[s][rg*4 + rr] = (b0, b1)
        #pragma unroll
        for (int p = 0; p < 2; ++p) {
            float l0, h0, l1, h1;
            asm("mov.b64 {%0,%1}, %2;" : "=f"(l0), "=f"(h0) : "l"(acc2[p][0]));
            asm("mov.b64 {%0,%1}, %2;" : "=f"(l1), "=f"(h1) : "l"(acc2[p][1]));
            red_s[s][rg * 4 + 2 * p]     = make_float2(l0, l1);
            red_s[s][rg * 4 + 2 * p + 1] = make_float2(h0, h1);
        }
        __syncthreads();

        // reduce + cell + broadcast (64 reducer threads)
        if (tid < 64) {
            const float* rp = (const float*)red_s;
            float pre[4];
            #pragma unroll
            for (int g = 0; g < 4; ++g) {
                float sum = xgv[g];
                #pragma unroll
                for (int ss = 0; ss < 8; ++ss)
                    sum += rp[(ss * 128 + g * 32 + uu) * 2 + bb];
                pre[g] = sum;
            }
            float iv = fast_sig(pre[0]);
            float fv = fast_sig(pre[1]);
            float gv = fast_tanh(pre[2]);
            float ov = fast_sig(pre[3]);
            c_reg = fv * c_reg + iv * gv;
            float hh = ov * fast_tanh(c_reg);

            if (!last) {
                ull hv2;
                asm("mov.b64 %0, {%1,%1};" : "=l"(hv2) : "f"(hh));
                const uint32_t laddr = hbase[buf ^ 1] + (uint32_t)(u0 + uu) * 16
                                     + (uint32_t)bb * 8;
                const uint32_t lmbar = mb_a[buf ^ 1];
                #pragma unroll
                for (int p = 0; p < 8; ++p) ST_ASYNC_B64(laddr, lmbar, p, hv2);
            }
            if (dec) g_ah[(size_t)(bglob * T_ + t) * H_ + u0 + uu] = __float2half(hh);
        }

        if (step == S_ - 1) load_wp(wp, Whh_dec, rg, s, u0);   // overlap with wait
    }
}

// =================== K3: output projection (fp16 mma.sync) =================
#define PROJ_SMEM (2 * 32768)

__device__ __forceinline__ void ldm_x4(uint32_t& r0, uint32_t& r1, uint32_t& r2, uint32_t& r3,
                                       uint32_t addr) {
    asm volatile("ldmatrix.sync.aligned.m8n8.x4.shared.b16 {%0,%1,%2,%3}, [%4];"
                 : "=r"(r0), "=r"(r1), "=r"(r2), "=r"(r3) : "r"(addr));
}
__device__ __forceinline__ void ldm_x2(uint32_t& r0, uint32_t& r1, uint32_t addr) {
    asm volatile("ldmatrix.sync.aligned.m8n8.x2.shared.b16 {%0,%1}, [%2];"
                 : "=r"(r0), "=r"(r1) : "r"(addr));
}
__device__ __forceinline__ void mma16816(float* d, const uint32_t* a, const uint32_t* b) {
    asm volatile(
        "mma.sync.aligned.m16n8k16.row.col.f32.f16.f16.f32 "
        "{%0,%1,%2,%3}, {%4,%5,%6,%7}, {%8,%9}, {%0,%1,%2,%3};"
        : "+f"(d[0]), "+f"(d[1]), "+f"(d[2]), "+f"(d[3])
        : "r"(a[0]), "r"(a[1]), "r"(a[2]), "r"(a[3]), "r"(b[0]), "r"(b[1]));
}

__global__ void __launch_bounds__(256, 2) proj_kernel(const float* __restrict__ bout,
                                                      float* __restrict__ out)
{
    extern __shared__ char smem[];
    const uint32_t sbase = smem_to_u32(smem);
    const int tid  = threadIdx.x;
    const int lane = tid & 31;
    const int w    = tid >> 5;
    const int wm   = w >> 2;
    const int wn   = w & 3;
    const int m0   = blockIdx.x * 128;
    const int n0   = blockIdx.y * 128;

    auto issue_chunk = [&](int c, int st) {
        const uint32_t abuf = sbase + st * 32768;
        const uint32_t bbuf = abuf + 16384;
        const __half* Ag = g_ah + (size_t)m0 * H_ + c * 64;
        const __half* Bg = g_bh + (size_t)n0 * H_ + c * 64;
        #pragma unroll
        for (int j = 0; j < 4; ++j) {
            int fi = tid + j * 256;
            int row = fi >> 3, c8 = fi & 7;
            uint32_t soff = SWZ128((uint32_t)(row * 128 + c8 * 16));
            const void* ga = (const char*)(Ag + (size_t)row * H_ + c8 * 8);
            const void* gb = (const char*)(Bg + (size_t)row * H_ + c8 * 8);
            asm volatile("cp.async.cg.shared.global [%0], [%1], 16;" :: "r"(abuf + soff), "l"(ga));
            asm volatile("cp.async.cg.shared.global [%0], [%1], 16;" :: "r"(bbuf + soff), "l"(gb));
        }
        asm volatile("cp.async.commit_group;" ::: "memory");
    };

    float acc[4][4][4];
    #pragma unroll
    for (int i = 0; i < 4; ++i)
        #pragma unroll
        for (int j = 0; j < 4; ++j)
            #pragma unroll
            for (int k = 0; k < 4; ++k) acc[i][j][k] = 0.f;

    issue_chunk(0, 0);
    issue_chunk(1, 1);

    const int l16 = lane & 15;
    #pragma unroll 1
    for (int c = 0; c < 4; ++c) {
        if (c < 3) asm volatile("cp.async.wait_group 1;" ::: "memory");
        else       asm volatile("cp.async.wait_group 0;" ::: "memory");
        __syncthreads();

        const uint32_t abuf = sbase + (c & 1) * 32768;
        const uint32_t bbuf = abuf + 16384;

        #pragma unroll
        for (int ks = 0; ks < 4; ++ks) {
            uint32_t a[4][4], b[4][2];
            #pragma unroll
            for (int mi = 0; mi < 4; ++mi) {
                int row = wm * 64 + mi * 16 + l16;
                uint32_t off = (uint32_t)(row * 128 + ks * 32 + (lane >> 4) * 16);
                ldm_x4(a[mi][0], a[mi][1], a[mi][2], a[mi][3], abuf + SWZ128(off));
            }
            #pragma unroll
            for (int bi = 0; bi < 4; ++bi) {
                int row = wn * 32 + bi * 8 + (l16 & 7);
                uint32_t off = (uint32_t)(row * 128 + ks * 32 + (l16 >> 3) * 16);
                ldm_x2(b[bi][0], b[bi][1], bbuf + SWZ128(off));
            }
            #pragma unroll
            for (int mi = 0; mi < 4; ++mi)
                #pragma unroll
                for (int bi = 0; bi < 4; ++bi)
                    mma16816(acc[mi][bi], a[mi], b[bi]);
        }
        __syncthreads();
        if (c + 2 < 4) issue_chunk(c + 2, c & 1);
    }

    #pragma unroll
    for (int bi = 0; bi < 4; ++bi) {
        const int col = n0 + wn * 32 + bi * 8 + (lane & 3) * 2;
        const float2 bb2 = *(const float2*)(bout + col);
        #pragma unroll
        for (int mi = 0; mi < 4; ++mi) {
            const int row = m0 + wm * 64 + mi * 16 + (lane >> 2);
            float2 v0 = make_float2(acc[mi][bi][0] + bb2.x, acc[mi][bi][1] + bb2.y);
            float2 v1 = make_float2(acc[mi][bi][2] + bb2.x, acc[mi][bi][3] + bb2.y);
            *(float2*)(out + (size_t)row * V_ + col) = v0;
            *(float2*)(out + (size_t)(row + 8) * V_ + col) = v1;
        }
    }
}

// ============================= launch ======================================
extern "C" void kernel_launch(void* const* d_in, const int* in_sizes, int n_in,
                              void* d_out, int out_size) {
    const int*   x        = (const int*)d_in[0];
    const int*   y        = (const int*)d_in[1];
    const float* enc_emb  = (const float*)d_in[2];
    const float* dec_emb  = (const float*)d_in[3];
    const float* Wih_enc  = (const float*)d_in[4];
    const float* Whh_enc  = (const float*)d_in[5];
    const float* bih_enc  = (const float*)d_in[6];
    const float* bhh_enc  = (const float*)d_in[7];
    const float* Wih_dec  = (const float*)d_in[8];
    const float* Whh_dec  = (const float*)d_in[9];
    const float* bih_dec  = (const float*)d_in[10];
    const float* bhh_dec  = (const float*)d_in[11];
    const float* Wout     = (const float*)d_in[12];
    const float* bout     = (const float*)d_in[13];
    float*       out      = (float*)d_out;

    const int XG_SMEM = (256 * 132 + 32 * 132) * 4;

    cudaFuncSetAttribute(xg_kernel,  cudaFuncAttributeMaxDynamicSharedMemorySize, XG_SMEM);
    cudaFuncSetAttribute(proj_kernel, cudaFuncAttributeMaxDynamicSharedMemorySize, PROJ_SMEM);

    __half *bh;
    cudaGetSymbolAddress((void**)&bh, g_bh);

    tohalf_kernel<<<(V_ * H_ / 4 + 255) / 256, 256>>>(Wout, bh, V_ * H_ / 4);

    xg_kernel<<<1024, 256, XG_SMEM>>>(x, y, enc_emb, dec_emb,
                                      Wih_enc, bih_enc, bhh_enc,
                                      Wih_dec, bih_dec, bhh_dec);

    rec_kernel<<<128, 256>>>(Whh_enc, Whh_dec);

    proj_kernel<<<dim3(32, V_ / 128), 256, PROJ_SMEM>>>(bout, out);
}